// round 1
// baseline (speedup 1.0000x reference)
#include <cuda_runtime.h>
#include <cub/cub.cuh>
#include <cstdint>

// Problem geometry: 8 inputs of shape (2, 64, 512, 512) f32.
// 128 histogram rows of 262144 elements each.
static constexpr int    ROWS    = 128;
static constexpr int    NR_LOG2 = 18;
static constexpr size_t NR      = (size_t)1 << NR_LOG2;   // 262144
static constexpr size_t TOT     = (size_t)ROWS * NR;      // 33554432
static constexpr float  PIF     = 3.14159274101257324f;   // float32(np.pi)

// ---------------------------------------------------------------------------
// Static device scratch (allocations are forbidden; __device__ globals are the
// sanctioned workaround).
// ---------------------------------------------------------------------------
__device__ __align__(256) unsigned long long g_kc_a[TOT];   // content keys (row<<31 | magbits)
__device__ __align__(256) unsigned long long g_kc_b[TOT];
__device__ __align__(256) unsigned int       g_vc_a[TOT];   // content payload: global index
__device__ __align__(256) unsigned int       g_vc_b[TOT];
__device__ __align__(256) unsigned long long g_ks_a[TOT];   // style keys
__device__ __align__(256) unsigned long long g_ks_b[TOT];
__device__ double g_sums[6];                                // sum|ch|,|cv|,|cd|,|sh|,|sv|,|sd|
static constexpr size_t TEMP_BYTES = (size_t)192 << 20;
__device__ __align__(256) unsigned char g_temp[TEMP_BYTES];

// ---------------------------------------------------------------------------
// Kernels
// ---------------------------------------------------------------------------
__global__ void zero_sums_k() {
    if (threadIdx.x < 6) g_sums[threadIdx.x] = 0.0;
}

// Fused global |x| sums for all six detail tensors (double accumulation).
__global__ void reduce6_k(const float* __restrict__ a0, const float* __restrict__ a1,
                          const float* __restrict__ a2, const float* __restrict__ a3,
                          const float* __restrict__ a4, const float* __restrict__ a5) {
    double acc0 = 0, acc1 = 0, acc2 = 0, acc3 = 0, acc4 = 0, acc5 = 0;
    size_t stride = (size_t)gridDim.x * blockDim.x;
    for (size_t i = (size_t)blockIdx.x * blockDim.x + threadIdx.x; i < TOT; i += stride) {
        acc0 += fabsf(a0[i]);
        acc1 += fabsf(a1[i]);
        acc2 += fabsf(a2[i]);
        acc3 += fabsf(a3[i]);
        acc4 += fabsf(a4[i]);
        acc5 += fabsf(a5[i]);
    }
    double acc[6] = {acc0, acc1, acc2, acc3, acc4, acc5};
    // warp reduce
    #pragma unroll
    for (int b = 0; b < 6; b++) {
        #pragma unroll
        for (int o = 16; o > 0; o >>= 1)
            acc[b] += __shfl_down_sync(0xffffffffu, acc[b], o);
    }
    __shared__ double smem[6][8];
    int w = threadIdx.x >> 5, l = threadIdx.x & 31;
    if (l == 0) {
        #pragma unroll
        for (int b = 0; b < 6; b++) smem[b][w] = acc[b];
    }
    __syncthreads();
    if (threadIdx.x == 0) {
        int nw = blockDim.x >> 5;
        #pragma unroll
        for (int b = 0; b < 6; b++) {
            double t = 0;
            for (int i = 0; i < nw; i++) t += smem[b][i];
            atomicAdd(&g_sums[b], t);
        }
    }
}

// Build sort keys: non-negative float bits are order-preserving as uint32.
// Tag the row id in bits [31,38) so one device-wide 38-bit radix sort is a
// segmented sort over all 128 rows.
__global__ void prep_k(const float* __restrict__ ca, const float* __restrict__ sa,
                       unsigned long long* __restrict__ kc,
                       unsigned int* __restrict__ vc,
                       unsigned long long* __restrict__ ks) {
    size_t i = (size_t)blockIdx.x * blockDim.x + threadIdx.x;
    if (i >= TOT) return;
    unsigned long long row = (unsigned long long)(i >> NR_LOG2);
    unsigned int cb = __float_as_uint(fabsf(ca[i]));
    unsigned int sb = __float_as_uint(fabsf(sa[i]));
    kc[i] = (row << 31) | (unsigned long long)cb;
    vc[i] = (unsigned int)i;
    ks[i] = (row << 31) | (unsigned long long)sb;
}

// Detail bands: out = |c| * (mean|s|/mean|c|) * 1.8 * cos(0.7*pc + 0.3*ps)
__global__ void detail_out_k(const float* __restrict__ ch, const float* __restrict__ cv,
                             const float* __restrict__ cd, const float* __restrict__ sh,
                             const float* __restrict__ sv, const float* __restrict__ sd,
                             float* __restrict__ out) {
    size_t i = (size_t)blockIdx.x * blockDim.x + threadIdx.x;
    if (i >= TOT) return;
    const double invN = 1.0 / (double)TOT;
    float mch = (float)(g_sums[0] * invN);
    float mcv = (float)(g_sums[1] * invN);
    float mcd = (float)(g_sums[2] * invN);
    float msh = (float)(g_sums[3] * invN);
    float msv = (float)(g_sums[4] * invN);
    float msd = (float)(g_sums[5] * invN);
    float rh = msh / mch;
    float rv = msv / mcv;
    float rd = msd / mcd;

    {
        float c = ch[i], s = sh[i];
        float pc = (c < 0.0f) ? PIF : 0.0f;
        float ps = (s < 0.0f) ? PIF : 0.0f;
        out[TOT + i] = ((fabsf(c) * rh) * 1.8f) * cosf(0.7f * pc + 0.3f * ps);
    }
    {
        float c = cv[i], s = sv[i];
        float pc = (c < 0.0f) ? PIF : 0.0f;
        float ps = (s < 0.0f) ? PIF : 0.0f;
        out[2 * TOT + i] = ((fabsf(c) * rv) * 1.8f) * cosf(0.7f * pc + 0.3f * ps);
    }
    {
        float c = cd[i], s = sd[i];
        float pc = (c < 0.0f) ? PIF : 0.0f;
        float ps = (s < 0.0f) ? PIF : 0.0f;
        out[3 * TOT + i] = ((fabsf(c) * rd) * 1.8f) * cosf(0.7f * pc + 0.3f * ps);
    }
}

// Approx band scatter: sorted position j in a row holds perm[j] (original index)
// and the j-th style order statistic. out[perm[j]] = t_sorted[j] * cos(blend).
__global__ void approx_out_k(const unsigned int* __restrict__ perm,
                             const unsigned long long* __restrict__ ks_sorted,
                             const float* __restrict__ ca,
                             const float* __restrict__ sa,
                             float* __restrict__ out) {
    size_t g = (size_t)blockIdx.x * blockDim.x + threadIdx.x;
    if (g >= TOT) return;
    unsigned int idx = perm[g];
    float mag = __uint_as_float((unsigned int)(ks_sorted[g] & 0x7FFFFFFFull));
    float c = __ldg(ca + idx);
    float s = __ldg(sa + idx);
    float pc = (c < 0.0f) ? PIF : 0.0f;
    float ps = (s < 0.0f) ? PIF : 0.0f;
    out[idx] = mag * cosf(0.8f * pc + 0.2f * ps);
}

// ---------------------------------------------------------------------------
// Launch
// ---------------------------------------------------------------------------
extern "C" void kernel_launch(void* const* d_in, const int* in_sizes, int n_in,
                              void* d_out, int out_size) {
    const float* ca = (const float*)d_in[0];
    const float* sa = (const float*)d_in[1];
    const float* ch = (const float*)d_in[2];
    const float* cv = (const float*)d_in[3];
    const float* cd = (const float*)d_in[4];
    const float* sh = (const float*)d_in[5];
    const float* sv = (const float*)d_in[6];
    const float* sd = (const float*)d_in[7];
    float* out = (float*)d_out;

    void *kc_a, *kc_b, *vc_a, *vc_b, *ks_a, *ks_b, *tmp;
    cudaGetSymbolAddress(&kc_a, g_kc_a);
    cudaGetSymbolAddress(&kc_b, g_kc_b);
    cudaGetSymbolAddress(&vc_a, g_vc_a);
    cudaGetSymbolAddress(&vc_b, g_vc_b);
    cudaGetSymbolAddress(&ks_a, g_ks_a);
    cudaGetSymbolAddress(&ks_b, g_ks_b);
    cudaGetSymbolAddress(&tmp,  g_temp);

    const int T = 256;
    const int B = (int)((TOT + T - 1) / T);   // 131072 blocks

    // Detail-band reduction (independent of the sorts).
    zero_sums_k<<<1, 32>>>();
    reduce6_k<<<1024, T>>>(ch, cv, cd, sh, sv, sd);

    // Build keys for both sorts.
    prep_k<<<B, T>>>(ca, sa,
                     (unsigned long long*)kc_a, (unsigned int*)vc_a,
                     (unsigned long long*)ks_a);

    // Content: stable SortPairs over 38 key bits -> per-row sort permutation.
    cub::DoubleBuffer<unsigned long long> dkc((unsigned long long*)kc_a,
                                              (unsigned long long*)kc_b);
    cub::DoubleBuffer<unsigned int>       dvc((unsigned int*)vc_a,
                                              (unsigned int*)vc_b);
    size_t temp_bytes = TEMP_BYTES;
    cub::DeviceRadixSort::SortPairs(tmp, temp_bytes, dkc, dvc, (int)TOT, 0, 38);

    // Style: SortKeys over 38 key bits -> per-row sorted magnitudes.
    cub::DoubleBuffer<unsigned long long> dks((unsigned long long*)ks_a,
                                              (unsigned long long*)ks_b);
    size_t temp_bytes2 = TEMP_BYTES;
    cub::DeviceRadixSort::SortKeys(tmp, temp_bytes2, dks, (int)TOT, 0, 38);

    // Elementwise outputs.
    detail_out_k<<<B, T>>>(ch, cv, cd, sh, sv, sd, out);
    approx_out_k<<<B, T>>>(dvc.Current(), dks.Current(), ca, sa, out);
}

// round 5
// speedup vs baseline: 1.8227x; 1.8227x over previous
#include <cuda_runtime.h>
#include <cub/cub.cuh>
#include <cstdint>

// Problem geometry: 8 inputs of shape (2, 64, 512, 512) f32.
// 128 histogram rows of 262144 elements each.
static constexpr int    ROWS    = 128;
static constexpr int    NR_LOG2 = 18;
static constexpr size_t NR      = (size_t)1 << NR_LOG2;   // 262144
static constexpr size_t TOT     = (size_t)ROWS * NR;      // 33554432 = 2^25

// cos blend factors (cast to float; differ from fp32-arithmetic reference by
// <1e-7, far below tolerance)
static constexpr float COS_02PI = 0.80901699437494745f;   // cos(0.2*pi)
static constexpr float COS_08PI = -0.80901699437494745f;  // cos(0.8*pi)
static constexpr float COS_03PI = 0.58778525229247314f;   // cos(0.3*pi)
static constexpr float COS_07PI = -0.58778525229247314f;  // cos(0.7*pi)

// ---------------------------------------------------------------------------
// Static device scratch (allocations forbidden; __device__ globals are the
// sanctioned workaround).
// ---------------------------------------------------------------------------
__device__ __align__(256) unsigned int g_kc_a[TOT];   // content keys: row<<24 | mag24
__device__ __align__(256) unsigned int g_kc_b[TOT];
__device__ __align__(256) unsigned int g_vc_a[TOT];   // payload: idx(25b) | pc<<25 | ps<<26
__device__ __align__(256) unsigned int g_vc_b[TOT];
__device__ __align__(256) unsigned int g_ks_a[TOT];   // style keys
__device__ __align__(256) unsigned int g_ks_b[TOT];
__device__ double g_sums[6];                          // sum|ch|,|cv|,|cd|,|sh|,|sv|,|sd|
static constexpr size_t TEMP_BYTES = (size_t)128 << 20;
__device__ __align__(256) unsigned char g_temp[TEMP_BYTES];

// ---------------------------------------------------------------------------
__global__ void zero_sums_k() {
    if (threadIdx.x < 6) g_sums[threadIdx.x] = 0.0;
}

// Fused global |x| sums for all six detail tensors (double accumulation),
// float4-vectorized grid-stride loop.
__global__ void reduce6_k(const float4* __restrict__ a0, const float4* __restrict__ a1,
                          const float4* __restrict__ a2, const float4* __restrict__ a3,
                          const float4* __restrict__ a4, const float4* __restrict__ a5) {
    const size_t N4 = TOT / 4;
    double acc[6] = {0, 0, 0, 0, 0, 0};
    size_t stride = (size_t)gridDim.x * blockDim.x;
    for (size_t i = (size_t)blockIdx.x * blockDim.x + threadIdx.x; i < N4; i += stride) {
        float4 v;
        v = a0[i]; acc[0] += (double)(fabsf(v.x) + fabsf(v.y) + fabsf(v.z) + fabsf(v.w));
        v = a1[i]; acc[1] += (double)(fabsf(v.x) + fabsf(v.y) + fabsf(v.z) + fabsf(v.w));
        v = a2[i]; acc[2] += (double)(fabsf(v.x) + fabsf(v.y) + fabsf(v.z) + fabsf(v.w));
        v = a3[i]; acc[3] += (double)(fabsf(v.x) + fabsf(v.y) + fabsf(v.z) + fabsf(v.w));
        v = a4[i]; acc[4] += (double)(fabsf(v.x) + fabsf(v.y) + fabsf(v.z) + fabsf(v.w));
        v = a5[i]; acc[5] += (double)(fabsf(v.x) + fabsf(v.y) + fabsf(v.z) + fabsf(v.w));
    }
    #pragma unroll
    for (int b = 0; b < 6; b++) {
        #pragma unroll
        for (int o = 16; o > 0; o >>= 1)
            acc[b] += __shfl_down_sync(0xffffffffu, acc[b], o);
    }
    __shared__ double smem[6][8];
    int w = threadIdx.x >> 5, l = threadIdx.x & 31;
    if (l == 0) {
        #pragma unroll
        for (int b = 0; b < 6; b++) smem[b][w] = acc[b];
    }
    __syncthreads();
    if (threadIdx.x == 0) {
        int nw = blockDim.x >> 5;
        #pragma unroll
        for (int b = 0; b < 6; b++) {
            double t = 0;
            for (int i = 0; i < nw; i++) t += smem[b][i];
            atomicAdd(&g_sums[b], t);
        }
    }
}

// Build sort keys/payloads. Non-negative float bits are order-preserving as
// uint32; keep the top 24 bits (8 exp + 16 mantissa, rel. quantization 2^-16)
// and tag the row in bits [24,31): one device-wide 31-bit radix sort acts as a
// segmented sort over all 128 rows. Payload carries the global index (25 bits)
// plus both phase bits so the scatter kernel needs no random gathers.
__global__ void prep_k(const float4* __restrict__ ca4, const float4* __restrict__ sa4,
                       uint4* __restrict__ kc, uint4* __restrict__ vc,
                       uint4* __restrict__ ks) {
    size_t i = (size_t)blockIdx.x * blockDim.x + threadIdx.x;   // float4 index
    if (i >= TOT / 4) return;
    unsigned int row = (unsigned int)(i >> (NR_LOG2 - 2));
    unsigned int rtag = row << 24;
    float4 c = ca4[i];
    float4 s = sa4[i];
    unsigned int base = (unsigned int)(i * 4);

    uint4 k, v, t;
    k.x = rtag | (__float_as_uint(fabsf(c.x)) >> 7);
    k.y = rtag | (__float_as_uint(fabsf(c.y)) >> 7);
    k.z = rtag | (__float_as_uint(fabsf(c.z)) >> 7);
    k.w = rtag | (__float_as_uint(fabsf(c.w)) >> 7);
    t.x = rtag | (__float_as_uint(fabsf(s.x)) >> 7);
    t.y = rtag | (__float_as_uint(fabsf(s.y)) >> 7);
    t.z = rtag | (__float_as_uint(fabsf(s.z)) >> 7);
    t.w = rtag | (__float_as_uint(fabsf(s.w)) >> 7);
    v.x = (base + 0) | ((c.x < 0.0f) ? (1u << 25) : 0u) | ((s.x < 0.0f) ? (1u << 26) : 0u);
    v.y = (base + 1) | ((c.y < 0.0f) ? (1u << 25) : 0u) | ((s.y < 0.0f) ? (1u << 26) : 0u);
    v.z = (base + 2) | ((c.z < 0.0f) ? (1u << 25) : 0u) | ((s.z < 0.0f) ? (1u << 26) : 0u);
    v.w = (base + 3) | ((c.w < 0.0f) ? (1u << 25) : 0u) | ((s.w < 0.0f) ? (1u << 26) : 0u);
    kc[i] = k;
    vc[i] = v;
    ks[i] = t;
}

// Detail-band element: |c| * r * 1.8 * cos(0.7*pc + 0.3*ps), factor picked by
// the sign pair.
__device__ __forceinline__ float det_elem(float c, float s, float r) {
    float f = (c < 0.0f) ? ((s < 0.0f) ? -1.0f : COS_07PI)
                         : ((s < 0.0f) ? COS_03PI : 1.0f);
    return fabsf(c) * r * 1.8f * f;
}

__global__ void detail_out_k(const float4* __restrict__ ch, const float4* __restrict__ cv,
                             const float4* __restrict__ cd, const float4* __restrict__ sh,
                             const float4* __restrict__ sv, const float4* __restrict__ sd,
                             float4* __restrict__ out) {
    size_t i = (size_t)blockIdx.x * blockDim.x + threadIdx.x;
    const size_t N4 = TOT / 4;
    if (i >= N4) return;
    float rh = (float)(g_sums[3] / g_sums[0]);
    float rv = (float)(g_sums[4] / g_sums[1]);
    float rd = (float)(g_sums[5] / g_sums[2]);

    {
        float4 c = ch[i], s = sh[i], o;
        o.x = det_elem(c.x, s.x, rh); o.y = det_elem(c.y, s.y, rh);
        o.z = det_elem(c.z, s.z, rh); o.w = det_elem(c.w, s.w, rh);
        out[N4 + i] = o;
    }
    {
        float4 c = cv[i], s = sv[i], o;
        o.x = det_elem(c.x, s.x, rv); o.y = det_elem(c.y, s.y, rv);
        o.z = det_elem(c.z, s.z, rv); o.w = det_elem(c.w, s.w, rv);
        out[2 * N4 + i] = o;
    }
    {
        float4 c = cd[i], s = sd[i], o;
        o.x = det_elem(c.x, s.x, rd); o.y = det_elem(c.y, s.y, rd);
        o.z = det_elem(c.z, s.z, rd); o.w = det_elem(c.w, s.w, rd);
        out[3 * N4 + i] = o;
    }
}

// Approx band scatter element: sorted position j holds payload (orig idx +
// sign bits) and the j-th style order statistic (sorted style key).
// out[idx] = style_stat * cos(0.8*pc + 0.2*ps).
__device__ __forceinline__ void approx_emit(unsigned int pay, unsigned int key,
                                            float* __restrict__ out) {
    unsigned int idx = pay & 0x01FFFFFFu;
    float mag = __uint_as_float((key & 0x00FFFFFFu) << 7);
    bool pc = (pay >> 25) & 1u, ps = (pay >> 26) & 1u;
    float f = pc ? (ps ? -1.0f : COS_08PI) : (ps ? COS_02PI : 1.0f);
    out[idx] = mag * f;
}

__global__ void approx_out_k(const uint4* __restrict__ perm,
                             const uint4* __restrict__ ks_sorted,
                             float* __restrict__ out) {
    size_t i = (size_t)blockIdx.x * blockDim.x + threadIdx.x;
    if (i >= TOT / 4) return;
    uint4 p = perm[i];
    uint4 k = ks_sorted[i];
    approx_emit(p.x, k.x, out);
    approx_emit(p.y, k.y, out);
    approx_emit(p.z, k.z, out);
    approx_emit(p.w, k.w, out);
}

// ---------------------------------------------------------------------------
extern "C" void kernel_launch(void* const* d_in, const int* in_sizes, int n_in,
                              void* d_out, int out_size) {
    const float* ca = (const float*)d_in[0];
    const float* sa = (const float*)d_in[1];
    const float* ch = (const float*)d_in[2];
    const float* cv = (const float*)d_in[3];
    const float* cd = (const float*)d_in[4];
    const float* sh = (const float*)d_in[5];
    const float* sv = (const float*)d_in[6];
    const float* sd = (const float*)d_in[7];
    float* out = (float*)d_out;

    void *kc_a, *kc_b, *vc_a, *vc_b, *ks_a, *ks_b, *tmp;
    cudaGetSymbolAddress(&kc_a, g_kc_a);
    cudaGetSymbolAddress(&kc_b, g_kc_b);
    cudaGetSymbolAddress(&vc_a, g_vc_a);
    cudaGetSymbolAddress(&vc_b, g_vc_b);
    cudaGetSymbolAddress(&ks_a, g_ks_a);
    cudaGetSymbolAddress(&ks_b, g_ks_b);
    cudaGetSymbolAddress(&tmp,  g_temp);

    const int T = 256;
    const int B4 = (int)(TOT / 4 / T);   // 32768 blocks for float4 kernels

    // Detail-band reduction (independent of the sorts).
    zero_sums_k<<<1, 32>>>();
    reduce6_k<<<2048, T>>>((const float4*)ch, (const float4*)cv, (const float4*)cd,
                           (const float4*)sh, (const float4*)sv, (const float4*)sd);

    // Build keys/payloads for both sorts.
    prep_k<<<B4, T>>>((const float4*)ca, (const float4*)sa,
                      (uint4*)kc_a, (uint4*)vc_a, (uint4*)ks_a);

    // Content: stable SortPairs over 31 key bits -> per-row sort permutation
    // (payload also carries sign bits).
    cub::DoubleBuffer<unsigned int> dkc((unsigned int*)kc_a, (unsigned int*)kc_b);
    cub::DoubleBuffer<unsigned int> dvc((unsigned int*)vc_a, (unsigned int*)vc_b);
    size_t temp_bytes = TEMP_BYTES;
    cub::DeviceRadixSort::SortPairs(tmp, temp_bytes, dkc, dvc, (int)TOT, 0, 31);

    // Style: SortKeys over 31 key bits -> per-row sorted magnitudes.
    cub::DoubleBuffer<unsigned int> dks((unsigned int*)ks_a, (unsigned int*)ks_b);
    size_t temp_bytes2 = TEMP_BYTES;
    cub::DeviceRadixSort::SortKeys(tmp, temp_bytes2, dks, (int)TOT, 0, 31);

    // Elementwise outputs.
    detail_out_k<<<B4, T>>>((const float4*)ch, (const float4*)cv, (const float4*)cd,
                            (const float4*)sh, (const float4*)sv, (const float4*)sd,
                            (float4*)out);
    approx_out_k<<<B4, T>>>((const uint4*)dvc.Current(), (const uint4*)dks.Current(),
                            out);
}